// round 5
// baseline (speedup 1.0000x reference)
#include <cuda_runtime.h>
#include <math.h>

#define Bb 8
#define Cc 256
#define Ll 512
#define NG 32
#define NH 8
#define Ee 1024
#define NTOK (Bb*Cc)

// ---------------- scratch ----------------
__device__ float g_S1[Bb*Cc*Ll];
__device__ float g_S2[Bb*Cc*Ll];
__device__ float g_S3[Bb*Cc*Ll];
__device__ float g_T [Bb*Ll*768];
__device__ float g_WT[512*256*3];          // transposed conv weights (reused serially)
__device__ float g_stats[Bb*NG*2];
__device__ float g_rawsum[Bb*Ee];
__device__ int   g_cnt1[Bb*Ee];
__device__ int   g_idx1[NTOK];
__device__ int   g_idx2[NTOK];
__device__ float g_g1[NTOK];
__device__ float g_g2[NTOK];
__device__ int   g_ecnt[Ee];
__device__ int   g_elist[Ee*64];
__device__ float g_eout[NTOK*2*512];       // raw expert outputs per slot

__device__ __forceinline__ float gelu_f(float x) {
    return 0.5f * x * (1.0f + erff(x * 0.70710678118654752f));
}

// ---------------- elementwise add ----------------
__global__ void add_k(const float* __restrict__ x, const float* __restrict__ e, float* __restrict__ o) {
    int i = blockIdx.x * 256 + threadIdx.x;
    o[i] = x[i] + e[i];
}

// ---------------- groupnorm stats ----------------
__global__ void gnstats_k(const float* __restrict__ in) {
    __shared__ float rs[256], rq[256];
    int bg = blockIdx.x;
    const float* p = in + bg * 4096;
    float s = 0.f, q = 0.f;
    for (int i = threadIdx.x; i < 4096; i += 256) { float v = p[i]; s += v; q += v * v; }
    rs[threadIdx.x] = s; rq[threadIdx.x] = q;
    __syncthreads();
    for (int st = 128; st > 0; st >>= 1) {
        if (threadIdx.x < st) { rs[threadIdx.x] += rs[threadIdx.x + st]; rq[threadIdx.x] += rq[threadIdx.x + st]; }
        __syncthreads();
    }
    if (threadIdx.x == 0) {
        float mean = rs[0] * (1.f / 4096.f);
        float var  = rq[0] * (1.f / 4096.f) - mean * mean;
        g_stats[bg * 2]     = mean;
        g_stats[bg * 2 + 1] = rsqrtf(var + 1e-5f);
    }
}

// ---------------- groupnorm apply + gelu ----------------
__global__ void gngelu_k(const float* __restrict__ in, const float* __restrict__ sc,
                         const float* __restrict__ bi, float* __restrict__ out) {
    int i = blockIdx.x * 256 + threadIdx.x;
    int c = (i >> 9) & 255;
    int b = i >> 17;
    int bg = b * 32 + (c >> 3);
    float mean = g_stats[bg * 2], rstd = g_stats[bg * 2 + 1];
    float v = (in[i] - mean) * rstd * sc[c] + bi[c];
    out[i] = gelu_f(v);
}

// ---------------- weight transpose: w[co][ci][t] -> wT[(ci*3+t)][co] ----------------
__global__ void wtrans_k(const float* __restrict__ w, float* __restrict__ wT, int Cout) {
    int i = blockIdx.x * 256 + threadIdx.x;
    if (i < Cout * 768) {
        int co = i / 768, r = i - co * 768;
        wT[r * Cout + co] = w[i];
    }
}

// ---------------- conv1d k=3 broadcast-GEMM: thread=co, 32-l register tile ----------------
__global__ __launch_bounds__(256) void convB_k(
    const float* __restrict__ in, const float* __restrict__ wT, const float* __restrict__ bias,
    const float* __restrict__ resid, float* __restrict__ out, int Cout) {
    __shared__ float xs[256][35];
    int b = blockIdx.z;
    int l0 = blockIdx.x * 32;
    int co = blockIdx.y * 256 + threadIdx.x;
    // stage input tile [256 ci][34] (with halo, zero-padded)
    const float* ip = in + b * 256 * 512;
    for (int m = threadIdx.x; m < 256 * 34; m += 256) {
        int ci = m / 34, jj = m - ci * 34;
        int l = l0 - 1 + jj;
        xs[ci][jj] = (l >= 0 && l < 512) ? ip[ci * 512 + l] : 0.f;
    }
    __syncthreads();
    float acc[32];
    float bb = bias[co];
    #pragma unroll
    for (int j = 0; j < 32; j++) acc[j] = bb;
    #pragma unroll 2
    for (int ci = 0; ci < 256; ci++) {
        const float* xr = xs[ci];
        float w0 = wT[(ci * 3 + 0) * Cout + co];
        float w1 = wT[(ci * 3 + 1) * Cout + co];
        float w2 = wT[(ci * 3 + 2) * Cout + co];
        #pragma unroll
        for (int j = 0; j < 32; j++)
            acc[j] += xr[j] * w0 + xr[j + 1] * w1 + xr[j + 2] * w2;
    }
    __syncthreads();
    // stage results for coalesced stores
    #pragma unroll
    for (int j = 0; j < 32; j++) xs[threadIdx.x][j] = acc[j];
    __syncthreads();
    int warp = threadIdx.x >> 5, lane = threadIdx.x & 31;
    for (int r = 0; r < 32; r++) {
        int col = r * 8 + warp;                       // local co
        int cog = blockIdx.y * 256 + col;
        int oi = (b * Cout + cog) * 512 + l0 + lane;
        float v = xs[col][lane];
        if (resid) v += resid[oi];
        out[oi] = v;
    }
}

// ---------------- QKV: 384 threads, 2 f-values per thread, 32-l tile ----------------
__global__ __launch_bounds__(384) void qkv_k(const float* __restrict__ x, const float* __restrict__ w1,
                                             const float* __restrict__ b1, float* __restrict__ T) {
    __shared__ float xs[256][33];
    int b = blockIdx.x, l0 = blockIdx.y * 32;
    for (int i = threadIdx.x; i < 256 * 32; i += 384) {
        int c = i >> 5, j = i & 31;
        xs[c][j] = x[(b * 256 + c) * 512 + l0 + j];
    }
    __syncthreads();
    int f = threadIdx.x;
    float acc0[32], acc1[32];
    float b0 = b1[f], b1v = b1[f + 384];
    #pragma unroll
    for (int j = 0; j < 32; j++) { acc0[j] = b0; acc1[j] = b1v; }
    for (int c = 0; c < 256; c++) {
        float wa = w1[c * 768 + f];
        float wb = w1[c * 768 + f + 384];
        const float* xr = xs[c];
        #pragma unroll
        for (int j = 0; j < 32; j++) {
            float xv = xr[j];
            acc0[j] += xv * wa;
            acc1[j] += xv * wb;
        }
    }
    #pragma unroll
    for (int j = 0; j < 32; j++) {
        T[(b * 512 + l0 + j) * 768 + f]       = acc0[j];
        T[(b * 512 + l0 + j) * 768 + f + 384] = acc1[j];
    }
}

// ---------------- attention ----------------
__global__ __launch_bounds__(512) void attn_k(const float* __restrict__ T, float* __restrict__ O) {
    extern __shared__ float sm[];
    float* Ks = sm;
    float* Vs = sm + 512 * 32;
    int b = blockIdx.x, h = blockIdx.y, tid = threadIdx.x;
    for (int i = tid; i < 512 * 32; i += 512) {
        int k = i >> 5, d = i & 31;
        const float* base = T + (b * 512 + k) * 768 + (d * 24 + h * 3);
        Ks[i] = base[1];
        Vs[i] = base[2];
    }
    __syncthreads();
    float q[32];
    {
        const float* base = T + (b * 512 + tid) * 768 + h * 3;
        #pragma unroll
        for (int d = 0; d < 32; d++) q[d] = base[d * 24];
    }
    float m = -1e30f, s = 0.f, acc[32];
    #pragma unroll
    for (int d = 0; d < 32; d++) acc[d] = 0.f;
    const float scale = 0.17677669529663687f;
    for (int k = 0; k < 512; k++) {
        float dot = 0.f;
        const float* kr = Ks + k * 32;
        #pragma unroll
        for (int d = 0; d < 32; d++) dot += q[d] * kr[d];
        dot *= scale;
        float mn = fmaxf(m, dot);
        float corr = __expf(m - mn);
        float p = __expf(dot - mn);
        s = s * corr + p;
        const float* vr = Vs + k * 32;
        #pragma unroll
        for (int d = 0; d < 32; d++) acc[d] = acc[d] * corr + p * vr[d];
        m = mn;
    }
    float inv = 1.f / s;
    float* op = O + (b * 512 + tid) * 256 + h;
    #pragma unroll
    for (int d = 0; d < 32; d++) op[d * 8] = acc[d] * inv;
}

// ---------------- out projection: 128 threads, 2 co per thread ----------------
__global__ __launch_bounds__(128) void oproj_k(const float* __restrict__ O, const float* __restrict__ w2,
                                               const float* __restrict__ b2, const float* __restrict__ emb,
                                               float* __restrict__ out) {
    __shared__ float os[32][256];
    int b = blockIdx.x, l0 = blockIdx.y * 32;
    for (int i = threadIdx.x; i < 32 * 256; i += 128) {
        int j = i >> 8, c = i & 255;
        os[j][c] = O[(b * 512 + l0 + j) * 256 + c];
    }
    __syncthreads();
    int co = threadIdx.x;
    float acc0[32], acc1[32];
    float ba = b2[co], bbv = b2[co + 128];
    #pragma unroll
    for (int j = 0; j < 32; j++) { acc0[j] = ba; acc1[j] = bbv; }
    for (int c = 0; c < 256; c++) {
        float wa = w2[c * 256 + co];
        float wb = w2[c * 256 + co + 128];
        #pragma unroll
        for (int j = 0; j < 32; j++) {
            float xv = os[j][c];
            acc0[j] += xv * wa;
            acc1[j] += xv * wb;
        }
    }
    #pragma unroll
    for (int j = 0; j < 32; j++) {
        int oi = (b * 256 + co) * 512 + l0 + j;
        out[oi] = acc0[j] + emb[oi];
        int oi2 = (b * 256 + co + 128) * 512 + l0 + j;
        out[oi2] = acc1[j] + emb[oi2];
    }
}

// ---------------- zero rawsum + ecnt ----------------
__global__ void zero_k() {
    int i = blockIdx.x * 256 + threadIdx.x;
    if (i < Bb * Ee) g_rawsum[i] = 0.f;
    else if (i < Bb * Ee + Ee) g_ecnt[i - Bb * Ee] = 0;
}

// ---------------- gating: 4 tokens per block ----------------
__global__ __launch_bounds__(256) void gate_k(const float* __restrict__ X, const float* __restrict__ wg) {
    __shared__ float xv[4][512];
    __shared__ float red[256];
    __shared__ int redi[256];
    int t0 = blockIdx.x * 4, tid = threadIdx.x, b = t0 >> 8;
    for (int i = tid; i < 4 * 512; i += 256) {
        int tok = i >> 9, d = i & 511;
        xv[tok][d] = X[(t0 + tok) * 512 + d];
    }
    __syncthreads();
    int e0 = tid * 4;
    float acc[4][4];
    #pragma unroll
    for (int tk = 0; tk < 4; tk++)
        #pragma unroll
        for (int j = 0; j < 4; j++) acc[tk][j] = 0.f;
    for (int d = 0; d < 512; d++) {
        float4 w = *(const float4*)(wg + d * 1024 + e0);
        #pragma unroll
        for (int tk = 0; tk < 4; tk++) {
            float xd = xv[tk][d];
            acc[tk][0] += xd * w.x; acc[tk][1] += xd * w.y;
            acc[tk][2] += xd * w.z; acc[tk][3] += xd * w.w;
        }
    }
    float rs[4] = {0.f, 0.f, 0.f, 0.f};
    for (int tk = 0; tk < 4; tk++) {
        int t = t0 + tk;
        float l0 = acc[tk][0], l1 = acc[tk][1], l2 = acc[tk][2], l3 = acc[tk][3];
        float lm = fmaxf(fmaxf(l0, l1), fmaxf(l2, l3));
        red[tid] = lm; __syncthreads();
        for (int s = 128; s > 0; s >>= 1) { if (tid < s) red[tid] = fmaxf(red[tid], red[tid + s]); __syncthreads(); }
        float gmax = red[0]; __syncthreads();
        float e_0 = __expf(l0 - gmax), e_1 = __expf(l1 - gmax), e_2 = __expf(l2 - gmax), e_3 = __expf(l3 - gmax);
        red[tid] = e_0 + e_1 + e_2 + e_3; __syncthreads();
        for (int s = 128; s > 0; s >>= 1) { if (tid < s) red[tid] += red[tid + s]; __syncthreads(); }
        float inv = 1.f / red[0]; __syncthreads();
        rs[0] += e_0 * inv; rs[1] += e_1 * inv; rs[2] += e_2 * inv; rs[3] += e_3 * inv;
        // top1
        float bv = l0; int bi = e0;
        if (l1 > bv) { bv = l1; bi = e0 + 1; }
        if (l2 > bv) { bv = l2; bi = e0 + 2; }
        if (l3 > bv) { bv = l3; bi = e0 + 3; }
        red[tid] = bv; redi[tid] = bi; __syncthreads();
        for (int s = 128; s > 0; s >>= 1) {
            if (tid < s) {
                float ov = red[tid + s]; int oi = redi[tid + s];
                if (ov > red[tid] || (ov == red[tid] && oi < redi[tid])) { red[tid] = ov; redi[tid] = oi; }
            }
            __syncthreads();
        }
        float v1 = red[0]; int i1 = redi[0]; __syncthreads();
        // top2
        float m0 = l0, m1 = l1, m2 = l2, m3 = l3;
        if      (i1 == e0)     m0 = -3e38f;
        else if (i1 == e0 + 1) m1 = -3e38f;
        else if (i1 == e0 + 2) m2 = -3e38f;
        else if (i1 == e0 + 3) m3 = -3e38f;
        bv = m0; bi = e0;
        if (m1 > bv) { bv = m1; bi = e0 + 1; }
        if (m2 > bv) { bv = m2; bi = e0 + 2; }
        if (m3 > bv) { bv = m3; bi = e0 + 3; }
        red[tid] = bv; redi[tid] = bi; __syncthreads();
        for (int s = 128; s > 0; s >>= 1) {
            if (tid < s) {
                float ov = red[tid + s]; int oi = redi[tid + s];
                if (ov > red[tid] || (ov == red[tid] && oi < redi[tid])) { red[tid] = ov; redi[tid] = oi; }
            }
            __syncthreads();
        }
        if (tid == 0) {
            float v2 = red[0]; int i2 = redi[0];
            float ga = __expf(v1 - gmax) * inv;
            float gb = __expf(v2 - gmax) * inv;
            float den = ga + gb + 1e-9f;
            g_idx1[t] = i1; g_idx2[t] = i2;
            g_g1[t] = ga / den; g_g2[t] = gb / den;
        }
        __syncthreads();
    }
    #pragma unroll
    for (int j = 0; j < 4; j++)
        if (rs[j] != 0.f) atomicAdd(&g_rawsum[b * 1024 + e0 + j], rs[j]);
}

// ---------------- capacity walk ----------------
__global__ void cap_k() {
    __shared__ int c1[1024], c2[1024];
    int b = blockIdx.x;
    for (int i = threadIdx.x; i < 1024; i += 256) { c1[i] = 0; c2[i] = 0; }
    __syncthreads();
    if (threadIdx.x == 0) {
        for (int n = 0; n < 256; n++) {
            int t = b * 256 + n; int e = g_idx1[t];
            if (c1[e] >= 4) g_g1[t] = 0.f;
            c1[e]++;
        }
        for (int n = 0; n < 256; n++) {
            int t = b * 256 + n; int e = g_idx2[t];
            int p = c2[e] + min(c1[e], 4);
            if (p >= 4) g_g2[t] = 0.f;
            c2[e]++;
        }
    }
    __syncthreads();
    for (int i = threadIdx.x; i < 1024; i += 256) g_cnt1[b * 1024 + i] = c1[i];
}

// ---------------- aux loss ----------------
__global__ void loss_k(float* __restrict__ aux) {
    __shared__ float red[256];
    float s = 0.f;
    for (int i = threadIdx.x; i < Bb * Ee; i += 256) s += g_rawsum[i] * (float)g_cnt1[i];
    red[threadIdx.x] = s; __syncthreads();
    for (int st = 128; st > 0; st >>= 1) { if (threadIdx.x < st) red[threadIdx.x] += red[threadIdx.x + st]; __syncthreads(); }
    if (threadIdx.x == 0) *aux = red[0] * (0.01f * (float)Ee / ((float)Bb * 256.f * 256.f));
}

// ---------------- scatter tokens to expert lists ----------------
__global__ void scatter_k() {
    int t = blockIdx.x * 256 + threadIdx.x;
    if (t >= NTOK) return;
    if (g_g1[t] != 0.f) {
        int e = g_idx1[t];
        int p = atomicAdd(&g_ecnt[e], 1);
        g_elist[e * 64 + p] = t * 2;
    }
    if (g_g2[t] != 0.f) {
        int e = g_idx2[t];
        int p = atomicAdd(&g_ecnt[e], 1);
        g_elist[e * 64 + p] = t * 2 + 1;
    }
}

// ---------------- expert compute: one block per expert, L1-resident weights ----------------
__global__ __launch_bounds__(256) void expert_k(const float* __restrict__ X, const float* __restrict__ w1,
                                                const float* __restrict__ w2) {
    int e = blockIdx.x;
    int nt = g_ecnt[e];
    if (nt == 0) return;
    __shared__ float xs[8][512];
    __shared__ float hs[8][32];
    int tid = threadIdx.x;
    for (int base = 0; base < nt; base += 8) {
        int nb = min(8, nt - base);
        for (int i = tid; i < nb * 512; i += 256) {
            int ti = i >> 9, d = i & 511;
            int a = g_elist[e * 64 + base + ti];
            xs[ti][d] = X[(a >> 1) * 512 + d];
        }
        __syncthreads();
        int ti = tid >> 5, hid = tid & 31;
        if (ti < nb) {
            float hv = 0.f;
            const float* wp = w1 + (size_t)e * 512 * 32 + hid;
            const float* xr = xs[ti];
            #pragma unroll 8
            for (int d = 0; d < 512; d++) hv += xr[d] * wp[d * 32];
            hs[ti][hid] = gelu_f(hv);
        }
        __syncthreads();
        const float* wq = w2 + (size_t)e * 32 * 512;
        for (int q = 0; q < nb; q++) {
            float s0 = 0.f, s1 = 0.f;
            #pragma unroll
            for (int j = 0; j < 32; j++) {
                float h = hs[q][j];
                s0 += h * wq[j * 512 + tid];
                s1 += h * wq[j * 512 + tid + 256];
            }
            int a = g_elist[e * 64 + base + q];
            g_eout[(size_t)a * 512 + tid]       = s0;
            g_eout[(size_t)a * 512 + tid + 256] = s1;
        }
        __syncthreads();
    }
}

// ---------------- combine: weighted sum of two expert slots ----------------
__global__ void combine_k(float* __restrict__ o1, float* __restrict__ o2) {
    int i = blockIdx.x * 256 + threadIdx.x;
    int t = i >> 9;
    float g1 = g_g1[t], g2 = g_g2[t];
    float v = 0.f;
    if (g1 != 0.f) v += g1 * g_eout[(size_t)(t * 2) * 512 + (i & 511)];
    if (g2 != 0.f) v += g2 * g_eout[(size_t)(t * 2 + 1) * 512 + (i & 511)];
    o1[i] = v;
    o2[i] = v;
}

// ---------------- max pool ----------------
__global__ void pool_k(const float* __restrict__ y0, float* __restrict__ out) {
    int i = blockIdx.x * 256 + threadIdx.x;
    int j = i & 255, bc = i >> 8;
    const float* r = y0 + bc * 512;
    int l = 2 * j;
    float m = r[l];
    if (l > 0) m = fmaxf(m, r[l - 1]);
    m = fmaxf(m, r[l + 1]);
    out[i] = m;
}

// ---------------- launch ----------------
extern "C" void kernel_launch(void* const* d_in, const int* in_sizes, int n_in,
                              void* d_out, int out_size) {
    const float* x     = (const float*)d_in[0];
    const float* emb   = (const float*)d_in[1];
    const float* r1g1s = (const float*)d_in[2];
    const float* r1g1b = (const float*)d_in[3];
    const float* r1c1w = (const float*)d_in[4];
    const float* r1c1b = (const float*)d_in[5];
    const float* r1g2s = (const float*)d_in[6];
    const float* r1g2b = (const float*)d_in[7];
    const float* r1c2w = (const float*)d_in[8];
    const float* r1c2b = (const float*)d_in[9];
    const float* r2g1s = (const float*)d_in[10];
    const float* r2g1b = (const float*)d_in[11];
    const float* r2c1w = (const float*)d_in[12];
    const float* r2c1b = (const float*)d_in[13];
    const float* r2g2s = (const float*)d_in[14];
    const float* r2g2b = (const float*)d_in[15];
    const float* r2c2w = (const float*)d_in[16];
    const float* r2c2b = (const float*)d_in[17];
    const float* aw1   = (const float*)d_in[18];
    const float* ab1   = (const float*)d_in[19];
    const float* aw2   = (const float*)d_in[20];
    const float* ab2   = (const float*)d_in[21];
    const float* mwg   = (const float*)d_in[22];
    const float* mw1   = (const float*)d_in[23];
    const float* mw2   = (const float*)d_in[24];
    const float* ow    = (const float*)d_in[25];
    const float* ob    = (const float*)d_in[26];
    float* out = (float*)d_out;

    float *S1, *S2, *S3, *T, *WT;
    cudaGetSymbolAddress((void**)&S1, g_S1);
    cudaGetSymbolAddress((void**)&S2, g_S2);
    cudaGetSymbolAddress((void**)&S3, g_S3);
    cudaGetSymbolAddress((void**)&T,  g_T);
    cudaGetSymbolAddress((void**)&WT, g_WT);

    cudaFuncSetAttribute(attn_k, cudaFuncAttributeMaxDynamicSharedMemorySize, 131072);

    // res_block 1
    add_k<<<4096, 256>>>(x, emb, S1);
    gnstats_k<<<256, 256>>>(S1);
    gngelu_k<<<4096, 256>>>(S1, r1g1s, r1g1b, S2);
    wtrans_k<<<768, 256>>>(r1c1w, WT, 256);
    convB_k<<<dim3(16, 1, 8), 256>>>(S2, WT, r1c1b, nullptr, S3, 256);
    gnstats_k<<<256, 256>>>(S3);
    gngelu_k<<<4096, 256>>>(S3, r1g2s, r1g2b, S2);
    wtrans_k<<<768, 256>>>(r1c2w, WT, 256);
    convB_k<<<dim3(16, 1, 8), 256>>>(S2, WT, r1c2b, S1, S3, 256);

    // attention
    qkv_k<<<dim3(8, 16), 384>>>(S3, aw1, ab1, T);
    attn_k<<<dim3(8, 8), 512, 131072>>>(T, S2);
    oproj_k<<<dim3(8, 16), 128>>>(S2, aw2, ab2, emb, S1);

    // res_block 2
    gnstats_k<<<256, 256>>>(S1);
    gngelu_k<<<4096, 256>>>(S1, r2g1s, r2g1b, S2);
    wtrans_k<<<768, 256>>>(r2c1w, WT, 256);
    convB_k<<<dim3(16, 1, 8), 256>>>(S2, WT, r2c1b, nullptr, S3, 256);
    gnstats_k<<<256, 256>>>(S3);
    gngelu_k<<<4096, 256>>>(S3, r2g2s, r2g2b, S2);
    wtrans_k<<<768, 256>>>(r2c2w, WT, 256);
    convB_k<<<dim3(16, 1, 8), 256>>>(S2, WT, r2c2b, S1, S3, 256);

    // MoE
    zero_k<<<36, 256>>>();
    gate_k<<<512, 256>>>(S3, mwg);
    cap_k<<<8, 256>>>();
    loss_k<<<1, 256>>>(out + 2 * 1048576);
    scatter_k<<<8, 256>>>();
    expert_k<<<1024, 256>>>(S3, mw1, mw2);
    combine_k<<<4096, 256>>>(S2, out + 1048576);

    // output conv + maxpool
    wtrans_k<<<1536, 256>>>(ow, WT, 512);
    convB_k<<<dim3(16, 2, 8), 256>>>(S2, WT, ob, nullptr, T, 512);
    pool_k<<<4096, 256>>>(T, out);
}

// round 7
// speedup vs baseline: 1.2525x; 1.2525x over previous
#include <cuda_runtime.h>
#include <math.h>

#define Bb 8
#define Cc 256
#define Ll 512
#define NG 32
#define NH 8
#define Ee 1024
#define NTOK (Bb*Cc)

// ---------------- scratch ----------------
__device__ float g_S1[Bb*Cc*Ll];
__device__ float g_S2[Bb*Cc*Ll];
__device__ float g_S3[Bb*Cc*Ll];
__device__ float g_T [Bb*Ll*768];
__device__ float g_stats[Bb*NG*2];
__device__ float g_rawsum[Bb*Ee];
__device__ int   g_cnt1[Bb*Ee];
__device__ int   g_idx1[NTOK];
__device__ int   g_idx2[NTOK];
__device__ float g_g1[NTOK];
__device__ float g_g2[NTOK];
__device__ int   g_ecnt[Ee];
__device__ int   g_elist[Ee*64];
__device__ float g_eout[NTOK*2*512];

__device__ __forceinline__ float gelu_f(float x) {
    return 0.5f * x * (1.0f + erff(x * 0.70710678118654752f));
}

// ---------------- elementwise add ----------------
__global__ void add_k(const float* __restrict__ x, const float* __restrict__ e, float* __restrict__ o) {
    int i = blockIdx.x * 256 + threadIdx.x;
    o[i] = x[i] + e[i];
}

// ---------------- groupnorm stats ----------------
__global__ void gnstats_k(const float* __restrict__ in) {
    __shared__ float rs[256], rq[256];
    int bg = blockIdx.x;
    const float* p = in + bg * 4096;
    float s = 0.f, q = 0.f;
    for (int i = threadIdx.x; i < 4096; i += 256) { float v = p[i]; s += v; q += v * v; }
    rs[threadIdx.x] = s; rq[threadIdx.x] = q;
    __syncthreads();
    for (int st = 128; st > 0; st >>= 1) {
        if (threadIdx.x < st) { rs[threadIdx.x] += rs[threadIdx.x + st]; rq[threadIdx.x] += rq[threadIdx.x + st]; }
        __syncthreads();
    }
    if (threadIdx.x == 0) {
        float mean = rs[0] * (1.f / 4096.f);
        float var  = rq[0] * (1.f / 4096.f) - mean * mean;
        g_stats[bg * 2]     = mean;
        g_stats[bg * 2 + 1] = rsqrtf(var + 1e-5f);
    }
}

// ---------------- groupnorm apply + gelu ----------------
__global__ void gngelu_k(const float* __restrict__ in, const float* __restrict__ sc,
                         const float* __restrict__ bi, float* __restrict__ out) {
    int i = blockIdx.x * 256 + threadIdx.x;
    int c = (i >> 9) & 255;
    int b = i >> 17;
    int bg = b * 32 + (c >> 3);
    float mean = g_stats[bg * 2], rstd = g_stats[bg * 2 + 1];
    float v = (in[i] - mean) * rstd * sc[c] + bi[c];
    out[i] = gelu_f(v);
}

// ---------------- conv1d k=3: 16 co per block, weights in smem as float4 (4 co per LDS.128) ----------------
// grid: (4 l-tiles of 128, Cout/16, 8 batch), 128 threads (one l each)
__global__ __launch_bounds__(128) void conv16_k(
    const float* __restrict__ in, const float* __restrict__ w, const float* __restrict__ bias,
    const float* __restrict__ resid, float* __restrict__ out, int Cout) {
    __shared__ float4 ws4[256 * 3 * 4];          // [ci][tap][4 chunks of 4 co] = 48KB
    float* wsf = (float*)ws4;
    int b = blockIdx.z, co0 = blockIdx.y * 16;
    int l = blockIdx.x * 128 + threadIdx.x;
    // fill weights: wsf[(ci*3+t)*16 + cl] = w[(co0+cl)*768 + ci*3+t]
    for (int i = threadIdx.x; i < 16 * 768; i += 128) {
        int r = i >> 4, cl = i & 15;
        wsf[i] = w[(co0 + cl) * 768 + r];
    }
    __syncthreads();
    float acc[16];
    #pragma unroll
    for (int k = 0; k < 16; k++) acc[k] = bias[co0 + k];
    const float* ip = in + b * 256 * 512;
    #pragma unroll 2
    for (int ci = 0; ci < 256; ci++) {
        const float* row = ip + ci * 512;
        float xm = (l > 0)   ? __ldg(row + l - 1) : 0.f;
        float x0 = __ldg(row + l);
        float xp = (l < 511) ? __ldg(row + l + 1) : 0.f;
        const float4* wp = ws4 + ci * 12;
        #pragma unroll
        for (int q = 0; q < 4; q++) {
            float4 w0 = wp[q];           // tap 0
            float4 w1 = wp[4 + q];       // tap 1
            float4 w2 = wp[8 + q];       // tap 2
            acc[q*4+0] += xm * w0.x + x0 * w1.x + xp * w2.x;
            acc[q*4+1] += xm * w0.y + x0 * w1.y + xp * w2.y;
            acc[q*4+2] += xm * w0.z + x0 * w1.z + xp * w2.z;
            acc[q*4+3] += xm * w0.w + x0 * w1.w + xp * w2.w;
        }
    }
    int o0 = (b * Cout + co0) * 512 + l;
    if (resid) {
        #pragma unroll
        for (int k = 0; k < 16; k++) out[o0 + k * 512] = acc[k] + resid[o0 + k * 512];
    } else {
        #pragma unroll
        for (int k = 0; k < 16; k++) out[o0 + k * 512] = acc[k];
    }
}

// ---------------- QKV: 384 threads, 2 f-values per thread, 32-l tile ----------------
__global__ __launch_bounds__(384) void qkv_k(const float* __restrict__ x, const float* __restrict__ w1,
                                             const float* __restrict__ b1, float* __restrict__ T) {
    __shared__ float xs[256][33];
    int b = blockIdx.x, l0 = blockIdx.y * 32;
    for (int i = threadIdx.x; i < 256 * 32; i += 384) {
        int c = i >> 5, j = i & 31;
        xs[c][j] = x[(b * 256 + c) * 512 + l0 + j];
    }
    __syncthreads();
    int f = threadIdx.x;
    float acc0[32], acc1[32];
    float b0 = b1[f], b1v = b1[f + 384];
    #pragma unroll
    for (int j = 0; j < 32; j++) { acc0[j] = b0; acc1[j] = b1v; }
    for (int c = 0; c < 256; c++) {
        float wa = w1[c * 768 + f];
        float wb = w1[c * 768 + f + 384];
        const float* xr = xs[c];
        #pragma unroll
        for (int j = 0; j < 32; j++) {
            float xv = xr[j];
            acc0[j] += xv * wa;
            acc1[j] += xv * wb;
        }
    }
    #pragma unroll
    for (int j = 0; j < 32; j++) {
        T[(b * 512 + l0 + j) * 768 + f]       = acc0[j];
        T[(b * 512 + l0 + j) * 768 + f + 384] = acc1[j];
    }
}

// ---------------- attention ----------------
__global__ __launch_bounds__(512) void attn_k(const float* __restrict__ T, float* __restrict__ O) {
    extern __shared__ float sm[];
    float* Ks = sm;
    float* Vs = sm + 512 * 32;
    int b = blockIdx.x, h = blockIdx.y, tid = threadIdx.x;
    for (int i = tid; i < 512 * 32; i += 512) {
        int k = i >> 5, d = i & 31;
        const float* base = T + (b * 512 + k) * 768 + (d * 24 + h * 3);
        Ks[i] = base[1];
        Vs[i] = base[2];
    }
    __syncthreads();
    float q[32];
    {
        const float* base = T + (b * 512 + tid) * 768 + h * 3;
        #pragma unroll
        for (int d = 0; d < 32; d++) q[d] = base[d * 24];
    }
    float m = -1e30f, s = 0.f, acc[32];
    #pragma unroll
    for (int d = 0; d < 32; d++) acc[d] = 0.f;
    const float scale = 0.17677669529663687f;
    for (int k = 0; k < 512; k++) {
        float dot = 0.f;
        const float* kr = Ks + k * 32;
        #pragma unroll
        for (int d = 0; d < 32; d++) dot += q[d] * kr[d];
        dot *= scale;
        float mn = fmaxf(m, dot);
        float corr = __expf(m - mn);
        float p = __expf(dot - mn);
        s = s * corr + p;
        const float* vr = Vs + k * 32;
        #pragma unroll
        for (int d = 0; d < 32; d++) acc[d] = acc[d] * corr + p * vr[d];
        m = mn;
    }
    float inv = 1.f / s;
    float* op = O + (b * 512 + tid) * 256 + h;
    #pragma unroll
    for (int d = 0; d < 32; d++) op[d * 8] = acc[d] * inv;
}

// ---------------- out projection: 128 threads, 2 co per thread ----------------
__global__ __launch_bounds__(128) void oproj_k(const float* __restrict__ O, const float* __restrict__ w2,
                                               const float* __restrict__ b2, const float* __restrict__ emb,
                                               float* __restrict__ out) {
    __shared__ float os[32][256];
    int b = blockIdx.x, l0 = blockIdx.y * 32;
    for (int i = threadIdx.x; i < 32 * 256; i += 128) {
        int j = i >> 8, c = i & 255;
        os[j][c] = O[(b * 512 + l0 + j) * 256 + c];
    }
    __syncthreads();
    int co = threadIdx.x;
    float acc0[32], acc1[32];
    float ba = b2[co], bbv = b2[co + 128];
    #pragma unroll
    for (int j = 0; j < 32; j++) { acc0[j] = ba; acc1[j] = bbv; }
    for (int c = 0; c < 256; c++) {
        float wa = w2[c * 256 + co];
        float wb = w2[c * 256 + co + 128];
        #pragma unroll
        for (int j = 0; j < 32; j++) {
            float xv = os[j][c];
            acc0[j] += xv * wa;
            acc1[j] += xv * wb;
        }
    }
    #pragma unroll
    for (int j = 0; j < 32; j++) {
        int oi = (b * 256 + co) * 512 + l0 + j;
        out[oi] = acc0[j] + emb[oi];
        int oi2 = (b * 256 + co + 128) * 512 + l0 + j;
        out[oi2] = acc1[j] + emb[oi2];
    }
}

// ---------------- zero rawsum + ecnt ----------------
__global__ void zero_k() {
    int i = blockIdx.x * 256 + threadIdx.x;
    if (i < Bb * Ee) g_rawsum[i] = 0.f;
    else if (i < Bb * Ee + Ee) g_ecnt[i - Bb * Ee] = 0;
}

// ---------------- gating: 4 tokens per block ----------------
__global__ __launch_bounds__(256) void gate_k(const float* __restrict__ X, const float* __restrict__ wg) {
    __shared__ float xv[4][512];
    __shared__ float red[256];
    __shared__ int redi[256];
    int t0 = blockIdx.x * 4, tid = threadIdx.x, b = t0 >> 8;
    for (int i = tid; i < 4 * 512; i += 256) {
        int tok = i >> 9, d = i & 511;
        xv[tok][d] = X[(t0 + tok) * 512 + d];
    }
    __syncthreads();
    int e0 = tid * 4;
    float acc[4][4];
    #pragma unroll
    for (int tk = 0; tk < 4; tk++)
        #pragma unroll
        for (int j = 0; j < 4; j++) acc[tk][j] = 0.f;
    for (int d = 0; d < 512; d++) {
        float4 w = *(const float4*)(wg + d * 1024 + e0);
        #pragma unroll
        for (int tk = 0; tk < 4; tk++) {
            float xd = xv[tk][d];
            acc[tk][0] += xd * w.x; acc[tk][1] += xd * w.y;
            acc[tk][2] += xd * w.z; acc[tk][3] += xd * w.w;
        }
    }
    float rs[4] = {0.f, 0.f, 0.f, 0.f};
    for (int tk = 0; tk < 4; tk++) {
        int t = t0 + tk;
        float l0 = acc[tk][0], l1 = acc[tk][1], l2 = acc[tk][2], l3 = acc[tk][3];
        float lm = fmaxf(fmaxf(l0, l1), fmaxf(l2, l3));
        red[tid] = lm; __syncthreads();
        for (int s = 128; s > 0; s >>= 1) { if (tid < s) red[tid] = fmaxf(red[tid], red[tid + s]); __syncthreads(); }
        float gmax = red[0]; __syncthreads();
        float e_0 = __expf(l0 - gmax), e_1 = __expf(l1 - gmax), e_2 = __expf(l2 - gmax), e_3 = __expf(l3 - gmax);
        red[tid] = e_0 + e_1 + e_2 + e_3; __syncthreads();
        for (int s = 128; s > 0; s >>= 1) { if (tid < s) red[tid] += red[tid + s]; __syncthreads(); }
        float inv = 1.f / red[0]; __syncthreads();
        rs[0] += e_0 * inv; rs[1] += e_1 * inv; rs[2] += e_2 * inv; rs[3] += e_3 * inv;
        float bv = l0; int bi = e0;
        if (l1 > bv) { bv = l1; bi = e0 + 1; }
        if (l2 > bv) { bv = l2; bi = e0 + 2; }
        if (l3 > bv) { bv = l3; bi = e0 + 3; }
        red[tid] = bv; redi[tid] = bi; __syncthreads();
        for (int s = 128; s > 0; s >>= 1) {
            if (tid < s) {
                float ov = red[tid + s]; int oi = redi[tid + s];
                if (ov > red[tid] || (ov == red[tid] && oi < redi[tid])) { red[tid] = ov; redi[tid] = oi; }
            }
            __syncthreads();
        }
        float v1 = red[0]; int i1 = redi[0]; __syncthreads();
        float m0 = l0, m1 = l1, m2 = l2, m3 = l3;
        if      (i1 == e0)     m0 = -3e38f;
        else if (i1 == e0 + 1) m1 = -3e38f;
        else if (i1 == e0 + 2) m2 = -3e38f;
        else if (i1 == e0 + 3) m3 = -3e38f;
        bv = m0; bi = e0;
        if (m1 > bv) { bv = m1; bi = e0 + 1; }
        if (m2 > bv) { bv = m2; bi = e0 + 2; }
        if (m3 > bv) { bv = m3; bi = e0 + 3; }
        red[tid] = bv; redi[tid] = bi; __syncthreads();
        for (int s = 128; s > 0; s >>= 1) {
            if (tid < s) {
                float ov = red[tid + s]; int oi = redi[tid + s];
                if (ov > red[tid] || (ov == red[tid] && oi < redi[tid])) { red[tid] = ov; redi[tid] = oi; }
            }
            __syncthreads();
        }
        if (tid == 0) {
            float v2 = red[0]; int i2 = redi[0];
            float ga = __expf(v1 - gmax) * inv;
            float gb = __expf(v2 - gmax) * inv;
            float den = ga + gb + 1e-9f;
            g_idx1[t] = i1; g_idx2[t] = i2;
            g_g1[t] = ga / den; g_g2[t] = gb / den;
        }
        __syncthreads();
    }
    #pragma unroll
    for (int j = 0; j < 4; j++)
        if (rs[j] != 0.f) atomicAdd(&g_rawsum[b * 1024 + e0 + j], rs[j]);
}

// ---------------- capacity walk ----------------
__global__ void cap_k() {
    __shared__ int c1[1024], c2[1024];
    int b = blockIdx.x;
    for (int i = threadIdx.x; i < 1024; i += 256) { c1[i] = 0; c2[i] = 0; }
    __syncthreads();
    if (threadIdx.x == 0) {
        for (int n = 0; n < 256; n++) {
            int t = b * 256 + n; int e = g_idx1[t];
            if (c1[e] >= 4) g_g1[t] = 0.f;
            c1[e]++;
        }
        for (int n = 0; n < 256; n++) {
            int t = b * 256 + n; int e = g_idx2[t];
            int p = c2[e] + min(c1[e], 4);
            if (p >= 4) g_g2[t] = 0.f;
            c2[e]++;
        }
    }
    __syncthreads();
    for (int i = threadIdx.x; i < 1024; i += 256) g_cnt1[b * 1024 + i] = c1[i];
}

// ---------------- aux loss ----------------
__global__ void loss_k(float* __restrict__ aux) {
    __shared__ float red[256];
    float s = 0.f;
    for (int i = threadIdx.x; i < Bb * Ee; i += 256) s += g_rawsum[i] * (float)g_cnt1[i];
    red[threadIdx.x] = s; __syncthreads();
    for (int st = 128; st > 0; st >>= 1) { if (threadIdx.x < st) red[threadIdx.x] += red[threadIdx.x + st]; __syncthreads(); }
    if (threadIdx.x == 0) *aux = red[0] * (0.01f * (float)Ee / ((float)Bb * 256.f * 256.f));
}

// ---------------- scatter tokens to expert lists ----------------
__global__ void scatter_k() {
    int t = blockIdx.x * 256 + threadIdx.x;
    if (t >= NTOK) return;
    if (g_g1[t] != 0.f) {
        int e = g_idx1[t];
        int p = atomicAdd(&g_ecnt[e], 1);
        g_elist[e * 64 + p] = t * 2;
    }
    if (g_g2[t] != 0.f) {
        int e = g_idx2[t];
        int p = atomicAdd(&g_ecnt[e], 1);
        g_elist[e * 64 + p] = t * 2 + 1;
    }
}

// ---------------- expert compute: one block per expert ----------------
__global__ __launch_bounds__(256) void expert_k(const float* __restrict__ X, const float* __restrict__ w1,
                                                const float* __restrict__ w2) {
    int e = blockIdx.x;
    int nt = g_ecnt[e];
    if (nt == 0) return;
    __shared__ float xs[8][512];
    __shared__ float hs[8][32];
    int tid = threadIdx.x;
    for (int base = 0; base < nt; base += 8) {
        int nb = min(8, nt - base);
        for (int i = tid; i < nb * 512; i += 256) {
            int ti = i >> 9, d = i & 511;
            int a = g_elist[e * 64 + base + ti];
            xs[ti][d] = X[(a >> 1) * 512 + d];
        }
        __syncthreads();
        int ti = tid >> 5, hid = tid & 31;
        if (ti < nb) {
            float hv = 0.f;
            const float* wp = w1 + (size_t)e * 512 * 32 + hid;
            const float* xr = xs[ti];
            #pragma unroll 8
            for (int d = 0; d < 512; d++) hv += xr[d] * wp[d * 32];
            hs[ti][hid] = gelu_f(hv);
        }
        __syncthreads();
        const float* wq = w2 + (size_t)e * 32 * 512;
        for (int q = 0; q < nb; q++) {
            float s0 = 0.f, s1 = 0.f;
            #pragma unroll
            for (int j = 0; j < 32; j++) {
                float h = hs[q][j];
                s0 += h * wq[j * 512 + tid];
                s1 += h * wq[j * 512 + tid + 256];
            }
            int a = g_elist[e * 64 + base + q];
            g_eout[(size_t)a * 512 + tid]       = s0;
            g_eout[(size_t)a * 512 + tid + 256] = s1;
        }
        __syncthreads();
    }
}

// ---------------- combine ----------------
__global__ void combine_k(float* __restrict__ o1, float* __restrict__ o2) {
    int i = blockIdx.x * 256 + threadIdx.x;
    int t = i >> 9;
    float g1 = g_g1[t], g2 = g_g2[t];
    float v = 0.f;
    if (g1 != 0.f) v += g1 * g_eout[(size_t)(t * 2) * 512 + (i & 511)];
    if (g2 != 0.f) v += g2 * g_eout[(size_t)(t * 2 + 1) * 512 + (i & 511)];
    o1[i] = v;
    o2[i] = v;
}

// ---------------- max pool ----------------
__global__ void pool_k(const float* __restrict__ y0, float* __restrict__ out) {
    int i = blockIdx.x * 256 + threadIdx.x;
    int j = i & 255, bc = i >> 8;
    const float* r = y0 + bc * 512;
    int l = 2 * j;
    float m = r[l];
    if (l > 0) m = fmaxf(m, r[l - 1]);
    m = fmaxf(m, r[l + 1]);
    out[i] = m;
}

// ---------------- launch ----------------
extern "C" void kernel_launch(void* const* d_in, const int* in_sizes, int n_in,
                              void* d_out, int out_size) {
    const float* x     = (const float*)d_in[0];
    const float* emb   = (const float*)d_in[1];
    const float* r1g1s = (const float*)d_in[2];
    const float* r1g1b = (const float*)d_in[3];
    const float* r1c1w = (const float*)d_in[4];
    const float* r1c1b = (const float*)d_in[5];
    const float* r1g2s = (const float*)d_in[6];
    const float* r1g2b = (const float*)d_in[7];
    const float* r1c2w = (const float*)d_in[8];
    const float* r1c2b = (const float*)d_in[9];
    const float* r2g1s = (const float*)d_in[10];
    const float* r2g1b = (const float*)d_in[11];
    const float* r2c1w = (const float*)d_in[12];
    const float* r2c1b = (const float*)d_in[13];
    const float* r2g2s = (const float*)d_in[14];
    const float* r2g2b = (const float*)d_in[15];
    const float* r2c2w = (const float*)d_in[16];
    const float* r2c2b = (const float*)d_in[17];
    const float* aw1   = (const float*)d_in[18];
    const float* ab1   = (const float*)d_in[19];
    const float* aw2   = (const float*)d_in[20];
    const float* ab2   = (const float*)d_in[21];
    const float* mwg   = (const float*)d_in[22];
    const float* mw1   = (const float*)d_in[23];
    const float* mw2   = (const float*)d_in[24];
    const float* ow    = (const float*)d_in[25];
    const float* ob    = (const float*)d_in[26];
    float* out = (float*)d_out;

    float *S1, *S2, *S3, *T;
    cudaGetSymbolAddress((void**)&S1, g_S1);
    cudaGetSymbolAddress((void**)&S2, g_S2);
    cudaGetSymbolAddress((void**)&S3, g_S3);
    cudaGetSymbolAddress((void**)&T,  g_T);

    cudaFuncSetAttribute(attn_k, cudaFuncAttributeMaxDynamicSharedMemorySize, 131072);

    // res_block 1
    add_k<<<4096, 256>>>(x, emb, S1);
    gnstats_k<<<256, 256>>>(S1);
    gngelu_k<<<4096, 256>>>(S1, r1g1s, r1g1b, S2);
    conv16_k<<<dim3(4, 16, 8), 128>>>(S2, r1c1w, r1c1b, nullptr, S3, 256);
    gnstats_k<<<256, 256>>>(S3);
    gngelu_k<<<4096, 256>>>(S3, r1g2s, r1g2b, S2);
    conv16_k<<<dim3(4, 16, 8), 128>>>(S2, r1c2w, r1c2b, S1, S3, 256);

    // attention
    qkv_k<<<dim3(8, 16), 384>>>(S3, aw1, ab1, T);
    attn_k<<<dim3(8, 8), 512, 131072>>>(T, S2);
    oproj_k<<<dim3(8, 16), 128>>>(S2, aw2, ab2, emb, S1);

    // res_block 2
    gnstats_k<<<256, 256>>>(S1);
    gngelu_k<<<4096, 256>>>(S1, r2g1s, r2g1b, S2);
    conv16_k<<<dim3(4, 16, 8), 128>>>(S2, r2c1w, r2c1b, nullptr, S3, 256);
    gnstats_k<<<256, 256>>>(S3);
    gngelu_k<<<4096, 256>>>(S3, r2g2s, r2g2b, S2);
    conv16_k<<<dim3(4, 16, 8), 128>>>(S2, r2c2w, r2c2b, S1, S3, 256);

    // MoE
    zero_k<<<36, 256>>>();
    gate_k<<<512, 256>>>(S3, mwg);
    cap_k<<<8, 256>>>();
    loss_k<<<1, 256>>>(out + 2 * 1048576);
    scatter_k<<<8, 256>>>();
    expert_k<<<1024, 256>>>(S3, mw1, mw2);
    combine_k<<<4096, 256>>>(S2, out + 1048576);

    // output conv + maxpool
    conv16_k<<<dim3(4, 32, 8), 128>>>(S2, ow, ob, nullptr, T, 512);
    pool_k<<<4096, 256>>>(T, out);
}

// round 8
// speedup vs baseline: 1.7308x; 1.3819x over previous
#include <cuda_runtime.h>
#include <math.h>

#define Bb 8
#define Cc 256
#define Ll 512
#define NG 32
#define NH 8
#define Ee 1024
#define NTOK (Bb*Cc)

typedef unsigned long long u64;

// ---------------- f32x2 helpers ----------------
__device__ __forceinline__ u64 fma2(u64 a, u64 b, u64 c) {
    u64 d; asm("fma.rn.f32x2 %0, %1, %2, %3;" : "=l"(d) : "l"(a), "l"(b), "l"(c)); return d;
}
__device__ __forceinline__ u64 mul2(u64 a, u64 b) {
    u64 d; asm("mul.rn.f32x2 %0, %1, %2;" : "=l"(d) : "l"(a), "l"(b)); return d;
}
__device__ __forceinline__ u64 add2(u64 a, u64 b) {
    u64 d; asm("add.rn.f32x2 %0, %1, %2;" : "=l"(d) : "l"(a), "l"(b)); return d;
}
__device__ __forceinline__ u64 pk2(float x, float y) {
    u64 d; asm("mov.b64 %0, {%1, %2};" : "=l"(d) : "r"(__float_as_uint(x)), "r"(__float_as_uint(y))); return d;
}
__device__ __forceinline__ float2 unpk2(u64 a) {
    unsigned int x, y; asm("mov.b64 {%0, %1}, %2;" : "=r"(x), "=r"(y) : "l"(a));
    return make_float2(__uint_as_float(x), __uint_as_float(y));
}

// ---------------- scratch ----------------
__device__ float g_S1[Bb*Cc*Ll];
__device__ float g_S2[Bb*Cc*Ll];
__device__ float g_S3[Bb*Cc*Ll];
__device__ float g_T [Bb*Ll*768];
__device__ float g_stats[Bb*NG*2];
__device__ float g_rawsum[Bb*Ee];
__device__ int   g_cnt1[Bb*Ee];
__device__ int   g_idx1[NTOK];
__device__ int   g_idx2[NTOK];
__device__ float g_g1[NTOK];
__device__ float g_g2[NTOK];
__device__ int   g_ecnt[Ee];
__device__ int   g_elist[Ee*64];
__device__ float g_eout[NTOK*2*512];

__device__ __forceinline__ float gelu_f(float x) {
    return 0.5f * x * (1.0f + erff(x * 0.70710678118654752f));
}

// ---------------- groupnorm stats (optional fused x+emb) ----------------
__global__ void gnstats_k(const float* __restrict__ in, const float* __restrict__ in2) {
    __shared__ float rs[256], rq[256];
    int bg = blockIdx.x;
    const float* p = in + bg * 4096;
    const float* p2 = in2 ? in2 + bg * 4096 : nullptr;
    float s = 0.f, q = 0.f;
    for (int i = threadIdx.x; i < 4096; i += 256) {
        float v = p[i];
        if (p2) v += p2[i];
        s += v; q += v * v;
    }
    rs[threadIdx.x] = s; rq[threadIdx.x] = q;
    __syncthreads();
    for (int st = 128; st > 0; st >>= 1) {
        if (threadIdx.x < st) { rs[threadIdx.x] += rs[threadIdx.x + st]; rq[threadIdx.x] += rq[threadIdx.x + st]; }
        __syncthreads();
    }
    if (threadIdx.x == 0) {
        float mean = rs[0] * (1.f / 4096.f);
        float var  = rq[0] * (1.f / 4096.f) - mean * mean;
        g_stats[bg * 2]     = mean;
        g_stats[bg * 2 + 1] = rsqrtf(var + 1e-5f);
    }
}

// ---------------- groupnorm apply + gelu (optional fused x+emb) ----------------
__global__ void gngelu_k(const float* __restrict__ in, const float* __restrict__ in2,
                         const float* __restrict__ sc, const float* __restrict__ bi,
                         float* __restrict__ out) {
    int i = blockIdx.x * 256 + threadIdx.x;
    int c = (i >> 9) & 255;
    int b = i >> 17;
    int bg = b * 32 + (c >> 3);
    float mean = g_stats[bg * 2], rstd = g_stats[bg * 2 + 1];
    float xv = in[i];
    if (in2) xv += in2[i];
    float v = (xv - mean) * rstd * sc[c] + bi[c];
    out[i] = gelu_f(v);
}

// ---------------- conv1d k=3: 16 co per block, 2 l per thread, f32x2 math ----------------
// grid: (2 l-tiles of 256, Cout/16, 8 batch), 128 threads
__global__ __launch_bounds__(128) void conv16_k(
    const float* __restrict__ in, const float* __restrict__ w, const float* __restrict__ bias,
    const float* __restrict__ residA, const float* __restrict__ residB,
    float* __restrict__ out, int Cout) {
    __shared__ float4 ws4[256 * 3 * 4];          // [ci][tap][4 chunks of 4 co] = 48KB
    float* wsf = (float*)ws4;
    int b = blockIdx.z, co0 = blockIdx.y * 16;
    int l  = blockIdx.x * 256 + threadIdx.x;     // first l
    int l2 = l + 128;                            // second l
    for (int i = threadIdx.x; i < 16 * 768; i += 128) {
        int r = i >> 4, cl = i & 15;
        wsf[i] = w[(co0 + cl) * 768 + r];
    }
    __syncthreads();
    u64 accA[8], accB[8];
    #pragma unroll
    for (int p = 0; p < 8; p++) {
        u64 bb = pk2(bias[co0 + 2*p], bias[co0 + 2*p + 1]);
        accA[p] = bb; accB[p] = bb;
    }
    const float* ip = in + b * 256 * 512;
    const ulonglong2* wd2 = (const ulonglong2*)wsf;
    #pragma unroll 2
    for (int ci = 0; ci < 256; ci++) {
        const float* row = ip + ci * 512;
        float am = (l > 0)    ? __ldg(row + l - 1)  : 0.f;
        float a0 = __ldg(row + l);
        float ap = __ldg(row + l + 1);               // l+1 <= 384, always in range
        float bm = __ldg(row + l2 - 1);              // l2-1 >= 127
        float b0 = __ldg(row + l2);
        float bp = (l2 < 511) ? __ldg(row + l2 + 1) : 0.f;
        u64 uam = pk2(am, am), ua0 = pk2(a0, a0), uap = pk2(ap, ap);
        u64 ubm = pk2(bm, bm), ub0 = pk2(b0, b0), ubp = pk2(bp, bp);
        const ulonglong2* wp = wd2 + ci * 12;
        #pragma unroll
        for (int j = 0; j < 4; j++) {
            ulonglong2 w0 = wp[j];                   // tap 0, co pairs (4j,4j+1),(4j+2,4j+3)
            ulonglong2 w1 = wp[4 + j];               // tap 1
            ulonglong2 w2 = wp[8 + j];               // tap 2
            accA[2*j]   = fma2(uam, w0.x, accA[2*j]);
            accA[2*j]   = fma2(ua0, w1.x, accA[2*j]);
            accA[2*j]   = fma2(uap, w2.x, accA[2*j]);
            accA[2*j+1] = fma2(uam, w0.y, accA[2*j+1]);
            accA[2*j+1] = fma2(ua0, w1.y, accA[2*j+1]);
            accA[2*j+1] = fma2(uap, w2.y, accA[2*j+1]);
            accB[2*j]   = fma2(ubm, w0.x, accB[2*j]);
            accB[2*j]   = fma2(ub0, w1.x, accB[2*j]);
            accB[2*j]   = fma2(ubp, w2.x, accB[2*j]);
            accB[2*j+1] = fma2(ubm, w0.y, accB[2*j+1]);
            accB[2*j+1] = fma2(ub0, w1.y, accB[2*j+1]);
            accB[2*j+1] = fma2(ubp, w2.y, accB[2*j+1]);
        }
    }
    int base = (b * Cout + co0) * 512;
    #pragma unroll
    for (int p = 0; p < 8; p++) {
        float2 va = unpk2(accA[p]);
        float2 vb = unpk2(accB[p]);
        int o0 = base + (2*p)     * 512;
        int o1 = base + (2*p + 1) * 512;
        float r0a = 0.f, r1a = 0.f, r0b = 0.f, r1b = 0.f;
        if (residA) {
            r0a = residA[o0 + l];  r1a = residA[o1 + l];
            r0b = residA[o0 + l2]; r1b = residA[o1 + l2];
            if (residB) {
                r0a += residB[o0 + l];  r1a += residB[o1 + l];
                r0b += residB[o0 + l2]; r1b += residB[o1 + l2];
            }
        }
        out[o0 + l]  = va.x + r0a;
        out[o1 + l]  = va.y + r1a;
        out[o0 + l2] = vb.x + r0b;
        out[o1 + l2] = vb.y + r1b;
    }
}

// ---------------- QKV: 384 threads, 2 f per thread, f32x2 over l-pairs ----------------
__global__ __launch_bounds__(384) void qkv_k(const float* __restrict__ x, const float* __restrict__ w1,
                                             const float* __restrict__ b1, float* __restrict__ T) {
    __shared__ float xs[256][32];
    int b = blockIdx.x, l0 = blockIdx.y * 32;
    for (int i = threadIdx.x; i < 256 * 32; i += 384) {
        int c = i >> 5, j = i & 31;
        xs[c][j] = x[(b * 256 + c) * 512 + l0 + j];
    }
    __syncthreads();
    int f = threadIdx.x;
    u64 A[16], B[16];
    {
        u64 ba = pk2(b1[f], b1[f]);
        u64 bb = pk2(b1[f + 384], b1[f + 384]);
        #pragma unroll
        for (int k = 0; k < 16; k++) { A[k] = ba; B[k] = bb; }
    }
    for (int c = 0; c < 256; c++) {
        float wa = w1[c * 768 + f];
        float wb = w1[c * 768 + f + 384];
        u64 ua = pk2(wa, wa), ub = pk2(wb, wb);
        const u64* xr = (const u64*)xs[c];
        #pragma unroll
        for (int k = 0; k < 16; k++) {
            u64 xv = xr[k];
            A[k] = fma2(xv, ua, A[k]);
            B[k] = fma2(xv, ub, B[k]);
        }
    }
    #pragma unroll
    for (int k = 0; k < 16; k++) {
        float2 va = unpk2(A[k]);
        float2 vb = unpk2(B[k]);
        T[(b * 512 + l0 + 2*k)     * 768 + f]       = va.x;
        T[(b * 512 + l0 + 2*k + 1) * 768 + f]       = va.y;
        T[(b * 512 + l0 + 2*k)     * 768 + f + 384] = vb.x;
        T[(b * 512 + l0 + 2*k + 1) * 768 + f + 384] = vb.y;
    }
}

// ---------------- attention: grid (b, h, 4 q-tiles), 128 threads, f32x2 + lazy rescale ----------------
__global__ __launch_bounds__(128) void attn_k(const float* __restrict__ T, float* __restrict__ O) {
    extern __shared__ float sm[];
    float* Kf = sm;
    float* Vf = sm + 512 * 32;
    int b = blockIdx.x, h = blockIdx.y, qt = blockIdx.z, tid = threadIdx.x;
    for (int i = tid; i < 512 * 32; i += 128) {
        int k = i >> 5, d = i & 31;
        const float* base = T + (b * 512 + k) * 768 + (d * 24 + h * 3);
        Kf[i] = base[1];
        Vf[i] = base[2];
    }
    __syncthreads();
    int q = qt * 128 + tid;
    const float scale = 0.17677669529663687f;    // 1/sqrt(32)
    u64 q2[16];
    {
        const float* base = T + (b * 512 + q) * 768 + h * 3;
        #pragma unroll
        for (int i = 0; i < 16; i++)
            q2[i] = pk2(base[(2*i) * 24] * scale, base[(2*i + 1) * 24] * scale);
    }
    const u64* K2 = (const u64*)Kf;
    const u64* V2 = (const u64*)Vf;
    float m = -1e30f, s = 0.f;
    u64 acc2[16];
    #pragma unroll
    for (int i = 0; i < 16; i++) acc2[i] = 0ull;
    #pragma unroll 2
    for (int k = 0; k < 512; k++) {
        const u64* kr = K2 + k * 16;
        u64 d0 = mul2(q2[0], kr[0]);
        u64 d1 = mul2(q2[1], kr[1]);
        u64 d2 = mul2(q2[2], kr[2]);
        u64 d3 = mul2(q2[3], kr[3]);
        #pragma unroll
        for (int i = 4; i < 16; i += 4) {
            d0 = fma2(q2[i],     kr[i],     d0);
            d1 = fma2(q2[i + 1], kr[i + 1], d1);
            d2 = fma2(q2[i + 2], kr[i + 2], d2);
            d3 = fma2(q2[i + 3], kr[i + 3], d3);
        }
        d0 = add2(d0, d1);
        d2 = add2(d2, d3);
        d0 = add2(d0, d2);
        float2 dd = unpk2(d0);
        float dot = dd.x + dd.y;
        const u64* vr = V2 + k * 16;
        if (dot <= m) {
            float p = __expf(dot - m);
            s += p;
            u64 p2 = pk2(p, p);
            #pragma unroll
            for (int i = 0; i < 16; i++) acc2[i] = fma2(p2, vr[i], acc2[i]);
        } else {
            float corr = __expf(m - dot);
            m = dot;
            s = s * corr + 1.f;
            u64 c2 = pk2(corr, corr);
            #pragma unroll
            for (int i = 0; i < 16; i++) acc2[i] = fma2(acc2[i], c2, vr[i]);   // acc*corr + v
        }
    }
    float inv = 1.f / s;
    float* op = O + (b * 512 + q) * 256 + h;
    #pragma unroll
    for (int i = 0; i < 16; i++) {
        float2 v = unpk2(acc2[i]);
        op[(2*i)     * 8] = v.x * inv;
        op[(2*i + 1) * 8] = v.y * inv;
    }
}

// ---------------- out projection: 128 threads, 2 co per thread, f32x2 over l-pairs ----------------
__global__ __launch_bounds__(128) void oproj_k(const float* __restrict__ O, const float* __restrict__ w2,
                                               const float* __restrict__ b2, const float* __restrict__ emb,
                                               float* __restrict__ out) {
    __shared__ float os[256][36];                // transposed; stride 36 keeps 8B align + spreads banks
    int b = blockIdx.x, l0 = blockIdx.y * 32;
    for (int i = threadIdx.x; i < 32 * 256; i += 128) {
        int c = i & 255, j = i >> 8;
        os[c][j] = O[(b * 512 + l0 + j) * 256 + c];
    }
    __syncthreads();
    int co = threadIdx.x;
    u64 A[16], B[16];
    {
        u64 ba = pk2(b2[co], b2[co]);
        u64 bb = pk2(b2[co + 128], b2[co + 128]);
        #pragma unroll
        for (int k = 0; k < 16; k++) { A[k] = ba; B[k] = bb; }
    }
    for (int c = 0; c < 256; c++) {
        float wa = w2[c * 256 + co];
        float wb = w2[c * 256 + co + 128];
        u64 ua = pk2(wa, wa), ub = pk2(wb, wb);
        const u64* xr = (const u64*)os[c];
        #pragma unroll
        for (int k = 0; k < 16; k++) {
            u64 xv = xr[k];
            A[k] = fma2(xv, ua, A[k]);
            B[k] = fma2(xv, ub, B[k]);
        }
    }
    #pragma unroll
    for (int k = 0; k < 16; k++) {
        float2 va = unpk2(A[k]);
        float2 vb = unpk2(B[k]);
        int oi  = (b * 256 + co) * 512 + l0 + 2*k;
        int oi2 = (b * 256 + co + 128) * 512 + l0 + 2*k;
        out[oi]      = va.x + emb[oi];
        out[oi + 1]  = va.y + emb[oi + 1];
        out[oi2]     = vb.x + emb[oi2];
        out[oi2 + 1] = vb.y + emb[oi2 + 1];
    }
}

// ---------------- zero rawsum + ecnt ----------------
__global__ void zero_k() {
    int i = blockIdx.x * 256 + threadIdx.x;
    if (i < Bb * Ee) g_rawsum[i] = 0.f;
    else if (i < Bb * Ee + Ee) g_ecnt[i - Bb * Ee] = 0;
}

// ---------------- gating: 4 tokens per block ----------------
__global__ __launch_bounds__(256) void gate_k(const float* __restrict__ X, const float* __restrict__ wg) {
    __shared__ float xv[4][512];
    __shared__ float red[256];
    __shared__ int redi[256];
    int t0 = blockIdx.x * 4, tid = threadIdx.x, b = t0 >> 8;
    for (int i = tid; i < 4 * 512; i += 256) {
        int tok = i >> 9, d = i & 511;
        xv[tok][d] = X[(t0 + tok) * 512 + d];
    }
    __syncthreads();
    int e0 = tid * 4;
    float acc[4][4];
    #pragma unroll
    for (int tk = 0; tk < 4; tk++)
        #pragma unroll
        for (int j = 0; j < 4; j++) acc[tk][j] = 0.f;
    for (int d = 0; d < 512; d++) {
        float4 w = *(const float4*)(wg + d * 1024 + e0);
        #pragma unroll
        for (int tk = 0; tk < 4; tk++) {
            float xd = xv[tk][d];
            acc[tk][0] += xd * w.x; acc[tk][1] += xd * w.y;
            acc[tk][2] += xd * w.z; acc[tk][3] += xd * w.w;
        }
    }
    float rs[4] = {0.f, 0.f, 0.f, 0.f};
    for (int tk = 0; tk < 4; tk++) {
        int t = t0 + tk;
        float l0 = acc[tk][0], l1 = acc[tk][1], l2 = acc[tk][2], l3 = acc[tk][3];
        float lm = fmaxf(fmaxf(l0, l1), fmaxf(l2, l3));
        red[tid] = lm; __syncthreads();
        for (int s = 128; s > 0; s >>= 1) { if (tid < s) red[tid] = fmaxf(red[tid], red[tid + s]); __syncthreads(); }
        float gmax = red[0]; __syncthreads();
        float e_0 = __expf(l0 - gmax), e_1 = __expf(l1 - gmax), e_2 = __expf(l2 - gmax), e_3 = __expf(l3 - gmax);
        red[tid] = e_0 + e_1 + e_2 + e_3; __syncthreads();
        for (int s = 128; s > 0; s >>= 1) { if (tid < s) red[tid] += red[tid + s]; __syncthreads(); }
        float inv = 1.f / red[0]; __syncthreads();
        rs[0] += e_0 * inv; rs[1] += e_1 * inv; rs[2] += e_2 * inv; rs[3] += e_3 * inv;
        float bv = l0; int bi = e0;
        if (l1 > bv) { bv = l1; bi = e0 + 1; }
        if (l2 > bv) { bv = l2; bi = e0 + 2; }
        if (l3 > bv) { bv = l3; bi = e0 + 3; }
        red[tid] = bv; redi[tid] = bi; __syncthreads();
        for (int s = 128; s > 0; s >>= 1) {
            if (tid < s) {
                float ov = red[tid + s]; int oi = redi[tid + s];
                if (ov > red[tid] || (ov == red[tid] && oi < redi[tid])) { red[tid] = ov; redi[tid] = oi; }
            }
            __syncthreads();
        }
        float v1 = red[0]; int i1 = redi[0]; __syncthreads();
        float m0 = l0, m1 = l1, m2 = l2, m3 = l3;
        if      (i1 == e0)     m0 = -3e38f;
        else if (i1 == e0 + 1) m1 = -3e38f;
        else if (i1 == e0 + 2) m2 = -3e38f;
        else if (i1 == e0 + 3) m3 = -3e38f;
        bv = m0; bi = e0;
        if (m1 > bv) { bv = m1; bi = e0 + 1; }
        if (m2 > bv) { bv = m2; bi = e0 + 2; }
        if (m3 > bv) { bv = m3; bi = e0 + 3; }
        red[tid] = bv; redi[tid] = bi; __syncthreads();
        for (int s = 128; s > 0; s >>= 1) {
            if (tid < s) {
                float ov = red[tid + s]; int oi = redi[tid + s];
                if (ov > red[tid] || (ov == red[tid] && oi < redi[tid])) { red[tid] = ov; redi[tid] = oi; }
            }
            __syncthreads();
        }
        if (tid == 0) {
            float v2 = red[0]; int i2 = redi[0];
            float ga = __expf(v1 - gmax) * inv;
            float gb = __expf(v2 - gmax) * inv;
            float den = ga + gb + 1e-9f;
            g_idx1[t] = i1; g_idx2[t] = i2;
            g_g1[t] = ga / den; g_g2[t] = gb / den;
        }
        __syncthreads();
    }
    #pragma unroll
    for (int j = 0; j < 4; j++)
        if (rs[j] != 0.f) atomicAdd(&g_rawsum[b * 1024 + e0 + j], rs[j]);
}

// ---------------- capacity walk ----------------
__global__ void cap_k() {
    __shared__ int c1[1024], c2[1024];
    int b = blockIdx.x;
    for (int i = threadIdx.x; i < 1024; i += 256) { c1[i] = 0; c2[i] = 0; }
    __syncthreads();
    if (threadIdx.x == 0) {
        for (int n = 0; n < 256; n++) {
            int t = b * 256 + n; int e = g_idx1[t];
            if (c1[e] >= 4) g_g1[t] = 0.f;
            c1[e]++;
        }
        for (int n = 0; n < 256; n++) {
            int t = b * 256 + n; int e = g_idx2[t];
            int p = c2[e] + min(c1[e], 4);
            if (p >= 4) g_g2[t] = 0.f;
            c2[e]++;
        }
    }
    __syncthreads();
    for (int i = threadIdx.x; i < 1024; i += 256) g_cnt1[b * 1024 + i] = c1[i];
}

// ---------------- aux loss ----------------
__global__ void loss_k(float* __restrict__ aux) {
    __shared__ float red[256];
    float s = 0.f;
    for (int i = threadIdx.x; i < Bb * Ee; i += 256) s += g_rawsum[i] * (float)g_cnt1[i];
    red[threadIdx.x] = s; __syncthreads();
    for (int st = 128; st > 0; st >>= 1) { if (threadIdx.x < st) red[threadIdx.x] += red[threadIdx.x + st]; __syncthreads(); }
    if (threadIdx.x == 0) *aux = red[0] * (0.01f * (float)Ee / ((float)Bb * 256.f * 256.f));
}

// ---------------- scatter tokens to expert lists ----------------
__global__ void scatter_k() {
    int t = blockIdx.x * 256 + threadIdx.x;
    if (t >= NTOK) return;
    if (g_g1[t] != 0.f) {
        int e = g_idx1[t];
        int p = atomicAdd(&g_ecnt[e], 1);
        g_elist[e * 64 + p] = t * 2;
    }
    if (g_g2[t] != 0.f) {
        int e = g_idx2[t];
        int p = atomicAdd(&g_ecnt[e], 1);
        g_elist[e * 64 + p] = t * 2 + 1;
    }
}

// ---------------- expert compute: one block per expert ----------------
__global__ __launch_bounds__(256) void expert_k(const float* __restrict__ X, const float* __restrict__ w1,
                                                const float* __restrict__ w2) {
    int e = blockIdx.x;
    int nt = g_ecnt[e];
    if (nt == 0) return;
    __shared__ float xs[8][512];
    __shared__ float hs[8][32];
    int tid = threadIdx.x;
    for (int base = 0; base < nt; base += 8) {
        int nb = min(8, nt - base);
        for (int i = tid; i < nb * 512; i += 256) {
            int ti = i >> 9, d = i & 511;
            int a = g_elist[e * 64 + base + ti];
            xs[ti][d] = X[(a >> 1) * 512 + d];
        }
        __syncthreads();
        int ti = tid >> 5, hid = tid & 31;
        if (ti < nb) {
            float hv = 0.f;
            const float* wp = w1 + (size_t)e * 512 * 32 + hid;
            const float* xr = xs[ti];
            #pragma unroll 8
            for (int d = 0; d < 512; d++) hv += xr[d] * wp[d * 32];
            hs[ti][hid] = gelu_f(hv);
        }
        __syncthreads();
        const float* wq = w2 + (size_t)e * 32 * 512;
        for (int q = 0; q < nb; q++) {
            float s0 = 0.f, s1 = 0.f;
            #pragma unroll
            for (int j = 0; j < 32; j++) {
                float h = hs[q][j];
                s0 += h * wq[j * 512 + tid];
                s1 += h * wq[j * 512 + tid + 256];
            }
            int a = g_elist[e * 64 + base + q];
            g_eout[(size_t)a * 512 + tid]       = s0;
            g_eout[(size_t)a * 512 + tid + 256] = s1;
        }
        __syncthreads();
    }
}

// ---------------- combine ----------------
__global__ void combine_k(float* __restrict__ o1, float* __restrict__ o2) {
    int i = blockIdx.x * 256 + threadIdx.x;
    int t = i >> 9;
    float g1 = g_g1[t], g2 = g_g2[t];
    float v = 0.f;
    if (g1 != 0.f) v += g1 * g_eout[(size_t)(t * 2) * 512 + (i & 511)];
    if (g2 != 0.f) v += g2 * g_eout[(size_t)(t * 2 + 1) * 512 + (i & 511)];
    o1[i] = v;
    o2[i] = v;
}

// ---------------- max pool ----------------
__global__ void pool_k(const float* __restrict__ y0, float* __restrict__ out) {
    int i = blockIdx.x * 256 + threadIdx.x;
    int j = i & 255, bc = i >> 8;
    const float* r = y0 + bc * 512;
    int l = 2 * j;
    float m = r[l];
    if (l > 0) m = fmaxf(m, r[l - 1]);
    m = fmaxf(m, r[l + 1]);
    out[i] = m;
}

// ---------------- launch ----------------
extern "C" void kernel_launch(void* const* d_in, const int* in_sizes, int n_in,
                              void* d_out, int out_size) {
    const float* x     = (const float*)d_in[0];
    const float* emb   = (const float*)d_in[1];
    const float* r1g1s = (const float*)d_in[2];
    const float* r1g1b = (const float*)d_in[3];
    const float* r1c1w = (const float*)d_in[4];
    const float* r1c1b = (const float*)d_in[5];
    const float* r1g2s = (const float*)d_in[6];
    const float* r1g2b = (const float*)d_in[7];
    const float* r1c2w = (const float*)d_in[8];
    const float* r1c2b = (const float*)d_in[9];
    const float* r2g1s = (const float*)d_in[10];
    const float* r2g1b = (const float*)d_in[11];
    const float* r2c1w = (const float*)d_in[12];
    const float* r2c1b = (const float*)d_in[13];
    const float* r2g2s = (const float*)d_in[14];
    const float* r2g2b = (const float*)d_in[15];
    const float* r2c2w = (const float*)d_in[16];
    const float* r2c2b = (const float*)d_in[17];
    const float* aw1   = (const float*)d_in[18];
    const float* ab1   = (const float*)d_in[19];
    const float* aw2   = (const float*)d_in[20];
    const float* ab2   = (const float*)d_in[21];
    const float* mwg   = (const float*)d_in[22];
    const float* mw1   = (const float*)d_in[23];
    const float* mw2   = (const float*)d_in[24];
    const float* ow    = (const float*)d_in[25];
    const float* ob    = (const float*)d_in[26];
    float* out = (float*)d_out;

    float *S1, *S2, *S3, *T;
    cudaGetSymbolAddress((void**)&S1, g_S1);
    cudaGetSymbolAddress((void**)&S2, g_S2);
    cudaGetSymbolAddress((void**)&S3, g_S3);
    cudaGetSymbolAddress((void**)&T,  g_T);

    cudaFuncSetAttribute(attn_k, cudaFuncAttributeMaxDynamicSharedMemorySize, 131072);

    // res_block 1 (x+emb fused into gn + conv residual)
    gnstats_k<<<256, 256>>>(x, emb);
    gngelu_k<<<4096, 256>>>(x, emb, r1g1s, r1g1b, S2);
    conv16_k<<<dim3(2, 16, 8), 128>>>(S2, r1c1w, r1c1b, nullptr, nullptr, S3, 256);
    gnstats_k<<<256, 256>>>(S3, nullptr);
    gngelu_k<<<4096, 256>>>(S3, nullptr, r1g2s, r1g2b, S2);
    conv16_k<<<dim3(2, 16, 8), 128>>>(S2, r1c2w, r1c2b, x, emb, S3, 256);

    // attention
    qkv_k<<<dim3(8, 16), 384>>>(S3, aw1, ab1, T);
    attn_k<<<dim3(8, 8, 4), 128, 131072>>>(T, S2);
    oproj_k<<<dim3(8, 16), 128>>>(S2, aw2, ab2, emb, S1);

    // res_block 2
    gnstats_k<<<256, 256>>>(S1, nullptr);
    gngelu_k<<<4096, 256>>>(S1, nullptr, r2g1s, r2g1b, S2);
    conv16_k<<<dim3(2, 16, 8), 128>>>(S2, r2c1w, r2c1b, nullptr, nullptr, S3, 256);
    gnstats_k<<<256, 256>>>(S3, nullptr);
    gngelu_k<<<4096, 256>>>(S3, nullptr, r2g2s, r2g2b, S2);
    conv16_k<<<dim3(2, 16, 8), 128>>>(S2, r2c2w, r2c2b, S1, nullptr, S3, 256);

    // MoE
    zero_k<<<36, 256>>>();
    gate_k<<<512, 256>>>(S3, mwg);
    cap_k<<<8, 256>>>();
    loss_k<<<1, 256>>>(out + 2 * 1048576);
    scatter_k<<<8, 256>>>();
    expert_k<<<1024, 256>>>(S3, mw1, mw2);
    combine_k<<<4096, 256>>>(S2, out + 1048576);

    // output conv + maxpool
    conv16_k<<<dim3(2, 32, 8), 128>>>(S2, ow, ob, nullptr, nullptr, T, 512);
    pool_k<<<4096, 256>>>(T, out);
}